// round 6
// baseline (speedup 1.0000x reference)
#include <cuda_runtime.h>

// LIF neuron scan, T=16:
//   u1 = mem*0.5 + x[t]*0.5 ; spike = (u1 > 1) ; mem = spike ? 0 : u1
// HBM-roofline streaming kernel (512 MB compulsory 1:1 R/W traffic,
// measured ceiling ~6.36 TB/s). Operating point from R1-R5:
//   - 1 float4 column per thread, interleaved t-loop (best measured BW)
//   - regs ~32 -> occ ~86% (warp count supplies MLP; per-thread batching
//     neutral (R2), occupancy loss fatal (R3), wave tail irrelevant (R5))
//   - 32-bit indexing, exact grid (4096 x 256), no guard branch
// R6 change: loads use .cs (evict-first) so the read-once input stream
// doesn't pollute L2; stores keep default write-back so L2 acts as a
// write-coalescing buffer for the output stream.

#define TSTEPS 16

__global__ void __launch_bounds__(256)
lif_scan_kernel(const float* __restrict__ x, float* __restrict__ out)
{
    const unsigned col = blockIdx.x * 256u + threadIdx.x;           // 0 .. 2^20-1
    const unsigned stride4 = 1u << 20;                              // float4 cols per timestep

    const float4* __restrict__ xp = reinterpret_cast<const float4*>(x) + col;
    float4* __restrict__ op = reinterpret_cast<float4*>(out) + col;

    float4 mem = make_float4(0.f, 0.f, 0.f, 0.f);

    #pragma unroll
    for (int t = 0; t < TSTEPS; ++t) {
        const unsigned off = (unsigned)t * stride4;
        const float4 xt = __ldcs(xp + off);   // evict-first: read-once stream

        float4 s;
        float u;
        u = fmaf(mem.x, 0.5f, xt.x * 0.5f); s.x = (u > 1.f) ? 1.f : 0.f; mem.x = (u > 1.f) ? 0.f : u;
        u = fmaf(mem.y, 0.5f, xt.y * 0.5f); s.y = (u > 1.f) ? 1.f : 0.f; mem.y = (u > 1.f) ? 0.f : u;
        u = fmaf(mem.z, 0.5f, xt.z * 0.5f); s.z = (u > 1.f) ? 1.f : 0.f; mem.z = (u > 1.f) ? 0.f : u;
        u = fmaf(mem.w, 0.5f, xt.w * 0.5f); s.w = (u > 1.f) ? 1.f : 0.f; mem.w = (u > 1.f) ? 0.f : u;

        op[off] = s;                           // default write-back: L2 absorbs
    }
}

extern "C" void kernel_launch(void* const* d_in, const int* in_sizes, int n_in,
                              void* d_out, int out_size)
{
    const float* x = (const float*)d_in[0];
    float* out = (float*)d_out;

    // 67,108,864 elements / 16 timesteps / 4 per float4 / 256 threads = 4096 CTAs exactly.
    lif_scan_kernel<<<4096, 256>>>(x, out);
}

// round 7
// speedup vs baseline: 1.0454x; 1.0454x over previous
#include <cuda_runtime.h>

// LIF neuron scan, T=16:
//   u1 = mem*0.5 + x[t]*0.5 ; spike = (u1 > 1) ; mem = spike ? 0 : u1
// HBM-roofline streaming kernel: 512 MB compulsory 1:1 R/W traffic at the
// measured ~6.36 TB/s mixed ceiling (~80% of 8 TB/s spec).
//
// Final operating point, each lever isolated over R1-R6:
//   - 1 float4 column per thread, interleaved t-loop   (best measured BW)
//   - plain LDG/STG: default cache policy beats .cs on either side (R2,R6)
//   - regs ~32 -> occ ~86%; warp count supplies MLP (R2 neutral, R3 fatal)
//   - wave-tail quantization irrelevant (R5)
//   - exact grid 4096 x 256, no guard, 32-bit offsets
// R7: pointer-bump addressing (IADD per step) instead of t*stride IMADs.

#define TSTEPS 16

__global__ void __launch_bounds__(256)
lif_scan_kernel(const float* __restrict__ x, float* __restrict__ out)
{
    const unsigned col = blockIdx.x * 256u + threadIdx.x;   // 0 .. 2^20-1
    const unsigned stride4 = 1u << 20;                      // float4 cols per timestep

    const float4* __restrict__ xp = reinterpret_cast<const float4*>(x) + col;
    float4* __restrict__ op = reinterpret_cast<float4*>(out) + col;

    float4 mem = make_float4(0.f, 0.f, 0.f, 0.f);

    #pragma unroll
    for (int t = 0; t < TSTEPS; ++t) {
        const float4 xt = *xp;

        float4 s;
        float u;
        u = fmaf(mem.x, 0.5f, xt.x * 0.5f); s.x = (u > 1.f) ? 1.f : 0.f; mem.x = (u > 1.f) ? 0.f : u;
        u = fmaf(mem.y, 0.5f, xt.y * 0.5f); s.y = (u > 1.f) ? 1.f : 0.f; mem.y = (u > 1.f) ? 0.f : u;
        u = fmaf(mem.z, 0.5f, xt.z * 0.5f); s.z = (u > 1.f) ? 1.f : 0.f; mem.z = (u > 1.f) ? 0.f : u;
        u = fmaf(mem.w, 0.5f, xt.w * 0.5f); s.w = (u > 1.f) ? 1.f : 0.f; mem.w = (u > 1.f) ? 0.f : u;

        *op = s;

        xp += stride4;   // single IADD per pointer per step
        op += stride4;
    }
}

extern "C" void kernel_launch(void* const* d_in, const int* in_sizes, int n_in,
                              void* d_out, int out_size)
{
    const float* x = (const float*)d_in[0];
    float* out = (float*)d_out;

    // 67,108,864 elements / 16 timesteps / 4 per float4 / 256 threads = 4096 CTAs exactly.
    lif_scan_kernel<<<4096, 256>>>(x, out);
}